// round 9
// baseline (speedup 1.0000x reference)
#include <cuda_runtime.h>
#include <cuda_bf16.h>
#include <math.h>

// ForwardBackwardImputer: out[b,t,:] = x[b, idx_fwd[b,t], :]
// mask[t] = all(|x[b,t,d]| <= 1e-6); idx_fwd = inclusive cummax(mask ? 0 : t).
// (Backward-fill branch of the reference is provably identical to x_fwd.)
//
// Kernel A: flattened, balanced mask + streaming copy-through (at HBM roofline)
// Kernel B: sliced scan+gather fill of the ~10% missing rows (balance-fixed)

#define L_SEQ 2048
#define D_FEAT 128
#define ROW_F4 (D_FEAT / 4)   // 32 float4 per timestep row
#define ATOL_F 1e-6f

#define A_THREADS 256
#define A_WARPS   8
#define A_GRID    1184        // 148 SMs * 8

#define B_THREADS 256
#define B_WARPS   8
#define B_SLICES  4           // CTAs per batch row
#define SLICE_LEN (L_SEQ / B_SLICES)   // 512 timesteps per CTA

// Max problem we support: 1024 batch rows of 2048 steps (2 MB).
__device__ unsigned char g_mask[1024 * L_SEQ];

// ---------------- Kernel A: mask + streaming copy-through ------------------
__global__ __launch_bounds__(A_THREADS)
void mask_copy_kernel(const float4* __restrict__ x, float4* __restrict__ out,
                      int ngroups) {   // ngroups = (B*L)/4
    const int lane = threadIdx.x & 31;
    const int wid  = threadIdx.x >> 5;
    const unsigned FULL = 0xffffffffu;
    const int totalW = gridDim.x * A_WARPS;

    for (int g = blockIdx.x * A_WARPS + wid; g < ngroups; g += totalW) {
        const int r0 = g << 2;  // flattened (b*L + t) row base
        float4 v0 = x[(r0 + 0) * ROW_F4 + lane];
        float4 v1 = x[(r0 + 1) * ROW_F4 + lane];
        float4 v2 = x[(r0 + 2) * ROW_F4 + lane];
        float4 v3 = x[(r0 + 3) * ROW_F4 + lane];

        bool z0 = (fabsf(v0.x) <= ATOL_F) & (fabsf(v0.y) <= ATOL_F) &
                  (fabsf(v0.z) <= ATOL_F) & (fabsf(v0.w) <= ATOL_F);
        bool z1 = (fabsf(v1.x) <= ATOL_F) & (fabsf(v1.y) <= ATOL_F) &
                  (fabsf(v1.z) <= ATOL_F) & (fabsf(v1.w) <= ATOL_F);
        bool z2 = (fabsf(v2.x) <= ATOL_F) & (fabsf(v2.y) <= ATOL_F) &
                  (fabsf(v2.z) <= ATOL_F) & (fabsf(v2.w) <= ATOL_F);
        bool z3 = (fabsf(v3.x) <= ATOL_F) & (fabsf(v3.y) <= ATOL_F) &
                  (fabsf(v3.z) <= ATOL_F) & (fabsf(v3.w) <= ATOL_F);

        unsigned m0 = __all_sync(FULL, z0);
        unsigned m1 = __all_sync(FULL, z1);
        unsigned m2 = __all_sync(FULL, z2);
        unsigned m3 = __all_sync(FULL, z3);

        if (!m0) __stcs(&out[(r0 + 0) * ROW_F4 + lane], v0);
        if (!m1) __stcs(&out[(r0 + 1) * ROW_F4 + lane], v1);
        if (!m2) __stcs(&out[(r0 + 2) * ROW_F4 + lane], v2);
        if (!m3) __stcs(&out[(r0 + 3) * ROW_F4 + lane], v3);

        if (lane == 0) {
            uchar4 mm = make_uchar4((unsigned char)m0, (unsigned char)m1,
                                    (unsigned char)m2, (unsigned char)m3);
            *reinterpret_cast<uchar4*>(&g_mask[r0]) = mm;
        }
    }
}

// ---------------- Kernel B: sliced scan + gather fill ----------------------
// grid = B * B_SLICES. Each CTA scans the full mask row (cheap, L2-hot) and
// fills only its SLICE_LEN-timestep slice -> 4x the CTAs, balanced wave.
__global__ __launch_bounds__(B_THREADS)
void fill_kernel(const float* __restrict__ x, float* __restrict__ out) {
    const int b     = blockIdx.x >> 2;           // B_SLICES == 4
    const int slice = blockIdx.x & 3;
    const float4* __restrict__ xb =
        reinterpret_cast<const float4*>(x + (size_t)b * L_SEQ * D_FEAT);
    float4* __restrict__ ob =
        reinterpret_cast<float4*>(out + (size_t)b * L_SEQ * D_FEAT);

    __shared__ unsigned char s_mask[L_SEQ];
    __shared__ short s_idx[L_SEQ];
    __shared__ int s_wtot[B_WARPS];

    const int tid  = threadIdx.x;
    const int lane = tid & 31;
    const int wid  = tid >> 5;
    const unsigned FULL = 0xffffffffu;

    // Load the full mask row (2 KB) coalesced: 256 threads x 8 bytes.
    {
        const ulonglong1* gm =
            reinterpret_cast<const ulonglong1*>(&g_mask[b * L_SEQ]);
        reinterpret_cast<ulonglong1*>(s_mask)[tid] = gm[tid];
    }
    __syncthreads();

    // Block-wide inclusive max-scan of (mask ? 0 : t), 8 steps per thread.
    const int t0 = tid << 3;
    int vloc[8];
    int run = 0;
    #pragma unroll
    for (int i = 0; i < 8; i++) {
        int t = t0 + i;
        int v = s_mask[t] ? 0 : t;
        if (v > run) run = v;
        vloc[i] = run;
    }

    int incl = run;
    #pragma unroll
    for (int o = 1; o < 32; o <<= 1) {
        int n = __shfl_up_sync(FULL, incl, o);
        if (lane >= o && n > incl) incl = n;
    }
    if (lane == 31) s_wtot[wid] = incl;
    int pre = __shfl_up_sync(FULL, incl, 1);
    int texcl = (lane == 0) ? 0 : pre;
    __syncthreads();

    if (tid == 0) {
        int r = 0;
        #pragma unroll
        for (int w = 0; w < B_WARPS; w++) {
            int tmp = s_wtot[w];
            s_wtot[w] = r;
            if (tmp > r) r = tmp;
        }
    }
    __syncthreads();

    int base = s_wtot[wid];
    if (texcl > base) base = texcl;
    #pragma unroll
    for (int i = 0; i < 8; i++) {
        int v = vloc[i] > base ? vloc[i] : base;
        s_idx[t0 + i] = (short)v;
    }
    __syncthreads();

    // Gather-fill missing rows in this CTA's slice only.
    const int s_lo = slice * SLICE_LEN;
    const int s_hi = s_lo + SLICE_LEN;
    for (int tt = s_lo + (wid << 2); tt < s_hi; tt += (B_WARPS << 2)) {
        uchar4 mm = *reinterpret_cast<const uchar4*>(&s_mask[tt]);
        // Prefetch indices before issuing gathers (break smem->LDG chain).
        int i0 = (int)s_idx[tt + 0];
        int i1 = (int)s_idx[tt + 1];
        int i2 = (int)s_idx[tt + 2];
        int i3 = (int)s_idx[tt + 3];
        if (mm.x) __stcs(&ob[(tt + 0) * ROW_F4 + lane], xb[i0 * ROW_F4 + lane]);
        if (mm.y) __stcs(&ob[(tt + 1) * ROW_F4 + lane], xb[i1 * ROW_F4 + lane]);
        if (mm.z) __stcs(&ob[(tt + 2) * ROW_F4 + lane], xb[i2 * ROW_F4 + lane]);
        if (mm.w) __stcs(&ob[(tt + 3) * ROW_F4 + lane], xb[i3 * ROW_F4 + lane]);
    }
}

extern "C" void kernel_launch(void* const* d_in, const int* in_sizes, int n_in,
                              void* d_out, int out_size) {
    const float* x = (const float*)d_in[0];
    float* out = (float*)d_out;
    const int B = in_sizes[0] / (L_SEQ * D_FEAT);
    const int ngroups = (B * L_SEQ) >> 2;

    mask_copy_kernel<<<A_GRID, A_THREADS>>>(
        reinterpret_cast<const float4*>(x),
        reinterpret_cast<float4*>(out), ngroups);
    fill_kernel<<<B * B_SLICES, B_THREADS>>>(x, out);
}

// round 10
// speedup vs baseline: 1.0696x; 1.0696x over previous
#include <cuda_runtime.h>
#include <cuda_bf16.h>
#include <math.h>

// ForwardBackwardImputer: out[b,t,:] = x[b, idx_fwd[b,t], :]
// mask[t] = all(|x[b,t,d]| <= 1e-6); idx_fwd = inclusive cummax(mask ? 0 : t).
// (Backward-fill branch of the reference is provably identical to x_fwd.)
//
// Kernel A: flattened, balanced mask + streaming copy-through (at HBM roofline)
// Kernel B: sliced scan + ballot-compacted gather fill (work-list, no
//           predicated walk over empty timesteps)

#define L_SEQ 2048
#define D_FEAT 128
#define ROW_F4 (D_FEAT / 4)   // 32 float4 per timestep row
#define ATOL_F 1e-6f

#define A_THREADS 256
#define A_WARPS   8
#define A_GRID    1184        // 148 SMs * 8

#define B_THREADS 256
#define B_WARPS   8
#define B_SLICES  4                      // CTAs per batch row
#define SLICE_LEN (L_SEQ / B_SLICES)     // 512 timesteps per CTA
#define WARP_SPAN (SLICE_LEN / B_WARPS)  // 64 timesteps per warp

// Max problem we support: 1024 batch rows of 2048 steps (2 MB).
__device__ unsigned char g_mask[1024 * L_SEQ];

// ---------------- Kernel A: mask + streaming copy-through ------------------
__global__ __launch_bounds__(A_THREADS)
void mask_copy_kernel(const float4* __restrict__ x, float4* __restrict__ out,
                      int ngroups) {   // ngroups = (B*L)/4
    const int lane = threadIdx.x & 31;
    const int wid  = threadIdx.x >> 5;
    const unsigned FULL = 0xffffffffu;
    const int totalW = gridDim.x * A_WARPS;

    for (int g = blockIdx.x * A_WARPS + wid; g < ngroups; g += totalW) {
        const int r0 = g << 2;  // flattened (b*L + t) row base
        float4 v0 = x[(r0 + 0) * ROW_F4 + lane];
        float4 v1 = x[(r0 + 1) * ROW_F4 + lane];
        float4 v2 = x[(r0 + 2) * ROW_F4 + lane];
        float4 v3 = x[(r0 + 3) * ROW_F4 + lane];

        bool z0 = (fabsf(v0.x) <= ATOL_F) & (fabsf(v0.y) <= ATOL_F) &
                  (fabsf(v0.z) <= ATOL_F) & (fabsf(v0.w) <= ATOL_F);
        bool z1 = (fabsf(v1.x) <= ATOL_F) & (fabsf(v1.y) <= ATOL_F) &
                  (fabsf(v1.z) <= ATOL_F) & (fabsf(v1.w) <= ATOL_F);
        bool z2 = (fabsf(v2.x) <= ATOL_F) & (fabsf(v2.y) <= ATOL_F) &
                  (fabsf(v2.z) <= ATOL_F) & (fabsf(v2.w) <= ATOL_F);
        bool z3 = (fabsf(v3.x) <= ATOL_F) & (fabsf(v3.y) <= ATOL_F) &
                  (fabsf(v3.z) <= ATOL_F) & (fabsf(v3.w) <= ATOL_F);

        unsigned m0 = __all_sync(FULL, z0);
        unsigned m1 = __all_sync(FULL, z1);
        unsigned m2 = __all_sync(FULL, z2);
        unsigned m3 = __all_sync(FULL, z3);

        if (!m0) __stcs(&out[(r0 + 0) * ROW_F4 + lane], v0);
        if (!m1) __stcs(&out[(r0 + 1) * ROW_F4 + lane], v1);
        if (!m2) __stcs(&out[(r0 + 2) * ROW_F4 + lane], v2);
        if (!m3) __stcs(&out[(r0 + 3) * ROW_F4 + lane], v3);

        if (lane == 0) {
            uchar4 mm = make_uchar4((unsigned char)m0, (unsigned char)m1,
                                    (unsigned char)m2, (unsigned char)m3);
            *reinterpret_cast<uchar4*>(&g_mask[r0]) = mm;
        }
    }
}

// ---------------- Kernel B: scan + compacted gather fill -------------------
// grid = B * B_SLICES. Each CTA scans the full mask row (L2-hot, cheap) and
// fills only the MISSING timesteps of its slice, via a ballot-compacted
// per-warp work list: exactly one LDG.128+STG.128 per lane per missing row.
__global__ __launch_bounds__(B_THREADS)
void fill_kernel(const float* __restrict__ x, float* __restrict__ out) {
    const int b     = blockIdx.x >> 2;           // B_SLICES == 4
    const int slice = blockIdx.x & 3;
    const float4* __restrict__ xb =
        reinterpret_cast<const float4*>(x + (size_t)b * L_SEQ * D_FEAT);
    float4* __restrict__ ob =
        reinterpret_cast<float4*>(out + (size_t)b * L_SEQ * D_FEAT);

    __shared__ unsigned char s_mask[L_SEQ];
    __shared__ short s_idx[L_SEQ];
    __shared__ int s_wtot[B_WARPS];
    __shared__ short s_list[B_WARPS][WARP_SPAN];  // per-warp missing-t list

    const int tid  = threadIdx.x;
    const int lane = tid & 31;
    const int wid  = tid >> 5;
    const unsigned FULL = 0xffffffffu;

    // Load the full mask row (2 KB): 256 threads x 8 bytes, coalesced.
    {
        const ulonglong1* gm =
            reinterpret_cast<const ulonglong1*>(&g_mask[b * L_SEQ]);
        reinterpret_cast<ulonglong1*>(s_mask)[tid] = gm[tid];
    }
    __syncthreads();

    // Block-wide inclusive max-scan of (mask ? 0 : t), 8 steps per thread.
    const int t0 = tid << 3;
    int vloc[8];
    int run = 0;
    #pragma unroll
    for (int i = 0; i < 8; i++) {
        int t = t0 + i;
        int v = s_mask[t] ? 0 : t;
        if (v > run) run = v;
        vloc[i] = run;
    }

    int incl = run;
    #pragma unroll
    for (int o = 1; o < 32; o <<= 1) {
        int n = __shfl_up_sync(FULL, incl, o);
        if (lane >= o && n > incl) incl = n;
    }
    if (lane == 31) s_wtot[wid] = incl;
    int pre = __shfl_up_sync(FULL, incl, 1);
    int texcl = (lane == 0) ? 0 : pre;
    __syncthreads();

    if (tid == 0) {
        int r = 0;
        #pragma unroll
        for (int w = 0; w < B_WARPS; w++) {
            int tmp = s_wtot[w];
            s_wtot[w] = r;
            if (tmp > r) r = tmp;
        }
    }
    __syncthreads();

    int base = s_wtot[wid];
    if (texcl > base) base = texcl;
    #pragma unroll
    for (int i = 0; i < 8; i++) {
        int v = vloc[i] > base ? vloc[i] : base;
        s_idx[t0 + i] = (short)v;
    }
    __syncthreads();

    // ---- Compaction: warp w owns timesteps [w_lo, w_lo + 64) of the slice.
    const int w_lo = slice * SLICE_LEN + wid * WARP_SPAN;
    int cnt = 0;
    #pragma unroll
    for (int half = 0; half < 2; half++) {
        int t = w_lo + half * 32 + lane;
        bool miss = (s_mask[t] != 0);
        unsigned bal = __ballot_sync(FULL, miss);
        int pos = __popc(bal & ((1u << lane) - 1u));
        if (miss) s_list[wid][cnt + pos] = (short)t;
        cnt += __popc(bal);
    }
    // cnt is uniform across the warp (same ballot everywhere).

    // ---- Fill: iterate ONLY real entries, 4 in flight for MLP.
    int i = 0;
    for (; i + 4 <= cnt; i += 4) {
        int ta = (int)s_list[wid][i + 0];
        int tb = (int)s_list[wid][i + 1];
        int tc = (int)s_list[wid][i + 2];
        int td = (int)s_list[wid][i + 3];
        int sa = (int)s_idx[ta];
        int sb = (int)s_idx[tb];
        int sc = (int)s_idx[tc];
        int sd = (int)s_idx[td];
        float4 va = xb[sa * ROW_F4 + lane];
        float4 vb = xb[sb * ROW_F4 + lane];
        float4 vc = xb[sc * ROW_F4 + lane];
        float4 vd = xb[sd * ROW_F4 + lane];
        __stcs(&ob[ta * ROW_F4 + lane], va);
        __stcs(&ob[tb * ROW_F4 + lane], vb);
        __stcs(&ob[tc * ROW_F4 + lane], vc);
        __stcs(&ob[td * ROW_F4 + lane], vd);
    }
    for (; i < cnt; i++) {
        int t = (int)s_list[wid][i];
        int s = (int)s_idx[t];
        __stcs(&ob[t * ROW_F4 + lane], xb[s * ROW_F4 + lane]);
    }
}

extern "C" void kernel_launch(void* const* d_in, const int* in_sizes, int n_in,
                              void* d_out, int out_size) {
    const float* x = (const float*)d_in[0];
    float* out = (float*)d_out;
    const int B = in_sizes[0] / (L_SEQ * D_FEAT);
    const int ngroups = (B * L_SEQ) >> 2;

    mask_copy_kernel<<<A_GRID, A_THREADS>>>(
        reinterpret_cast<const float4*>(x),
        reinterpret_cast<float4*>(out), ngroups);
    fill_kernel<<<B * B_SLICES, B_THREADS>>>(x, out);
}

// round 12
// speedup vs baseline: 1.0844x; 1.0139x over previous
#include <cuda_runtime.h>
#include <cuda_bf16.h>
#include <math.h>

// ForwardBackwardImputer: out[b,t,:] = x[b, idx_fwd[b,t], :]
// mask[t] = all(|x[b,t,d]| <= 1e-6); idx_fwd = inclusive cummax(mask ? 0 : t).
// (Backward-fill branch of the reference is provably identical to x_fwd.)
//
// Kernel A : flattened, balanced mask + streaming copy-through (HBM roofline)
// Kernel A2: per-row forward-fill index scan -> g_idx (tiny)
// Kernel B : warp-local ballot-compacted gather fill (no scan, no block syncs)

#define L_SEQ 2048
#define D_FEAT 128
#define ROW_F4 (D_FEAT / 4)   // 32 float4 per timestep row
#define ATOL_F 1e-6f

#define A_THREADS 256
#define A_WARPS   8
#define A_GRID    1184        // 148 SMs * 8

#define S_THREADS 256         // A2: 256 threads x 8 steps = 2048
#define S_WARPS   8

#define B_THREADS 256
#define B_WARPS   8
#define B_SLICES  4                      // CTAs per batch row
#define SLICE_LEN (L_SEQ / B_SLICES)     // 512 timesteps per CTA
#define WARP_SPAN 64                     // timesteps per warp in B

// Max problem we support: 1024 batch rows of 2048 steps.
__device__ unsigned char g_mask[1024 * L_SEQ];   // 2 MB
__device__ short         g_idx [1024 * L_SEQ];   // 4 MB

// ---------------- Kernel A: mask + streaming copy-through ------------------
__global__ __launch_bounds__(A_THREADS)
void mask_copy_kernel(const float4* __restrict__ x, float4* __restrict__ out,
                      int ngroups) {   // ngroups = (B*L)/4
    const int lane = threadIdx.x & 31;
    const int wid  = threadIdx.x >> 5;
    const unsigned FULL = 0xffffffffu;
    const int totalW = gridDim.x * A_WARPS;

    for (int g = blockIdx.x * A_WARPS + wid; g < ngroups; g += totalW) {
        const int r0 = g << 2;  // flattened (b*L + t) row base
        float4 v0 = x[(r0 + 0) * ROW_F4 + lane];
        float4 v1 = x[(r0 + 1) * ROW_F4 + lane];
        float4 v2 = x[(r0 + 2) * ROW_F4 + lane];
        float4 v3 = x[(r0 + 3) * ROW_F4 + lane];

        bool z0 = (fabsf(v0.x) <= ATOL_F) & (fabsf(v0.y) <= ATOL_F) &
                  (fabsf(v0.z) <= ATOL_F) & (fabsf(v0.w) <= ATOL_F);
        bool z1 = (fabsf(v1.x) <= ATOL_F) & (fabsf(v1.y) <= ATOL_F) &
                  (fabsf(v1.z) <= ATOL_F) & (fabsf(v1.w) <= ATOL_F);
        bool z2 = (fabsf(v2.x) <= ATOL_F) & (fabsf(v2.y) <= ATOL_F) &
                  (fabsf(v2.z) <= ATOL_F) & (fabsf(v2.w) <= ATOL_F);
        bool z3 = (fabsf(v3.x) <= ATOL_F) & (fabsf(v3.y) <= ATOL_F) &
                  (fabsf(v3.z) <= ATOL_F) & (fabsf(v3.w) <= ATOL_F);

        unsigned m0 = __all_sync(FULL, z0);
        unsigned m1 = __all_sync(FULL, z1);
        unsigned m2 = __all_sync(FULL, z2);
        unsigned m3 = __all_sync(FULL, z3);

        if (!m0) __stcs(&out[(r0 + 0) * ROW_F4 + lane], v0);
        if (!m1) __stcs(&out[(r0 + 1) * ROW_F4 + lane], v1);
        if (!m2) __stcs(&out[(r0 + 2) * ROW_F4 + lane], v2);
        if (!m3) __stcs(&out[(r0 + 3) * ROW_F4 + lane], v3);

        if (lane == 0) {
            uchar4 mm = make_uchar4((unsigned char)m0, (unsigned char)m1,
                                    (unsigned char)m2, (unsigned char)m3);
            *reinterpret_cast<uchar4*>(&g_mask[r0]) = mm;
        }
    }
}

// ---------------- Kernel A2: per-row forward-fill index scan ---------------
// One CTA per batch row. Thread tid owns timesteps [8*tid, 8*tid+8), whose
// mask bytes are exactly one aligned 64-bit load. Inclusive max-scan across
// the block, result written as one 16-byte coalesced store per thread.
__global__ __launch_bounds__(S_THREADS)
void scan_kernel() {
    const int b   = blockIdx.x;
    const int tid = threadIdx.x;
    const int lane = tid & 31;
    const int wid  = tid >> 5;
    const unsigned FULL = 0xffffffffu;

    __shared__ int s_wtot[S_WARPS];

    const int t0 = tid << 3;
    unsigned long long w =
        *reinterpret_cast<const unsigned long long*>(&g_mask[b * L_SEQ + t0]);

    int vloc[8];
    int run = 0;
    #pragma unroll
    for (int i = 0; i < 8; i++) {
        int missing = (int)((w >> (8 * i)) & 0xffULL);
        int v = missing ? 0 : (t0 + i);
        if (v > run) run = v;
        vloc[i] = run;
    }

    int incl = run;
    #pragma unroll
    for (int o = 1; o < 32; o <<= 1) {
        int n = __shfl_up_sync(FULL, incl, o);
        if (lane >= o && n > incl) incl = n;
    }
    if (lane == 31) s_wtot[wid] = incl;
    int pre = __shfl_up_sync(FULL, incl, 1);
    int texcl = (lane == 0) ? 0 : pre;
    __syncthreads();

    if (tid == 0) {
        int r = 0;
        #pragma unroll
        for (int ww = 0; ww < S_WARPS; ww++) {
            int tmp = s_wtot[ww];
            s_wtot[ww] = r;
            if (tmp > r) r = tmp;
        }
    }
    __syncthreads();

    int base = s_wtot[wid];
    if (texcl > base) base = texcl;

    // Pack 8 shorts into one uint4 store (16 B, coalesced).
    unsigned p[4];
    #pragma unroll
    for (int i = 0; i < 4; i++) {
        int lo = vloc[2 * i]     > base ? vloc[2 * i]     : base;
        int hi = vloc[2 * i + 1] > base ? vloc[2 * i + 1] : base;
        p[i] = (unsigned)(lo & 0xffff) | ((unsigned)hi << 16);
    }
    uint4 o4 = make_uint4(p[0], p[1], p[2], p[3]);
    *reinterpret_cast<uint4*>(&g_idx[b * L_SEQ + t0]) = o4;
}

// ---------------- Kernel B: warp-local compacted gather fill ---------------
// grid = B * B_SLICES, 8 warps/CTA, 64 timesteps/warp. No scan, no block
// barriers: ballot-compact missing steps, prefetch source indices, fill.
__global__ __launch_bounds__(B_THREADS)
void fill_kernel(const float* __restrict__ x, float* __restrict__ out) {
    const int b     = blockIdx.x >> 2;           // B_SLICES == 4
    const int slice = blockIdx.x & 3;
    const float4* __restrict__ xb =
        reinterpret_cast<const float4*>(x + (size_t)b * L_SEQ * D_FEAT);
    float4* __restrict__ ob =
        reinterpret_cast<float4*>(out + (size_t)b * L_SEQ * D_FEAT);

    __shared__ short s_list[B_WARPS][WARP_SPAN];
    __shared__ short s_src [B_WARPS][WARP_SPAN];

    const int lane = threadIdx.x & 31;
    const int wid  = threadIdx.x >> 5;
    const unsigned FULL = 0xffffffffu;
    const unsigned lt = (1u << lane) - 1u;

    const int w_lo = slice * SLICE_LEN + wid * WARP_SPAN;  // within row
    const int gbase = b * L_SEQ;

    unsigned char m0 = g_mask[gbase + w_lo + lane];
    unsigned char m1 = g_mask[gbase + w_lo + 32 + lane];

    unsigned bal0 = __ballot_sync(FULL, m0 != 0);
    unsigned bal1 = __ballot_sync(FULL, m1 != 0);
    int c0  = __popc(bal0);
    int cnt = c0 + __popc(bal1);
    if (cnt == 0) return;

    if (m0) s_list[wid][__popc(bal0 & lt)]      = (short)(w_lo + lane);
    if (m1) s_list[wid][c0 + __popc(bal1 & lt)] = (short)(w_lo + 32 + lane);
    __syncwarp();

    // Lane-parallel prefetch of source indices.
    for (int j = lane; j < cnt; j += 32)
        s_src[wid][j] = g_idx[gbase + (int)s_list[wid][j]];
    __syncwarp();

    int i = 0;
    for (; i + 4 <= cnt; i += 4) {
        int ta = (int)s_list[wid][i + 0];
        int tb = (int)s_list[wid][i + 1];
        int tc = (int)s_list[wid][i + 2];
        int td = (int)s_list[wid][i + 3];
        int sa = (int)s_src[wid][i + 0];
        int sb = (int)s_src[wid][i + 1];
        int sc = (int)s_src[wid][i + 2];
        int sd = (int)s_src[wid][i + 3];
        float4 va = xb[sa * ROW_F4 + lane];
        float4 vb = xb[sb * ROW_F4 + lane];
        float4 vc = xb[sc * ROW_F4 + lane];
        float4 vd = xb[sd * ROW_F4 + lane];
        __stcs(&ob[ta * ROW_F4 + lane], va);
        __stcs(&ob[tb * ROW_F4 + lane], vb);
        __stcs(&ob[tc * ROW_F4 + lane], vc);
        __stcs(&ob[td * ROW_F4 + lane], vd);
    }
    for (; i < cnt; i++) {
        int t = (int)s_list[wid][i];
        int s = (int)s_src[wid][i];
        __stcs(&ob[t * ROW_F4 + lane], xb[s * ROW_F4 + lane]);
    }
}

extern "C" void kernel_launch(void* const* d_in, const int* in_sizes, int n_in,
                              void* d_out, int out_size) {
    const float* x = (const float*)d_in[0];
    float* out = (float*)d_out;
    const int B = in_sizes[0] / (L_SEQ * D_FEAT);
    const int ngroups = (B * L_SEQ) >> 2;

    mask_copy_kernel<<<A_GRID, A_THREADS>>>(
        reinterpret_cast<const float4*>(x),
        reinterpret_cast<float4*>(out), ngroups);
    scan_kernel<<<B, S_THREADS>>>();
    fill_kernel<<<B * B_SLICES, B_THREADS>>>(x, out);
}

// round 13
// speedup vs baseline: 1.0927x; 1.0076x over previous
#include <cuda_runtime.h>
#include <cuda_bf16.h>
#include <math.h>

// ForwardBackwardImputer: out[b,t,:] = x[b, idx_fwd[b,t], :]
// mask[t] = all(|x[b,t,d]| <= 1e-6); idx_fwd = inclusive cummax(mask ? 0 : t).
// (Backward-fill branch of the reference is provably identical to x_fwd;
//  verified rel_err==0 across rounds.)
//
// Kernel A: flattened, balanced mask + streaming copy-through (HBM roofline)
// Kernel B: warp-self-contained gather fill — each warp derives all forward-
//           fill indices from mask ballots (no global scan kernel, no g_idx).

#define L_SEQ 2048
#define D_FEAT 128
#define ROW_F4 (D_FEAT / 4)   // 32 float4 per timestep row
#define ATOL_F 1e-6f

#define A_THREADS 256
#define A_WARPS   8
#define A_GRID    1184        // 148 SMs * 8

#define B_THREADS 256
#define B_WARPS   8
#define B_SLICES  4                      // CTAs per batch row
#define SLICE_LEN (L_SEQ / B_SLICES)     // 512 timesteps per CTA
#define WARP_SPAN 64                     // timesteps per warp in B

// Max problem we support: 1024 batch rows of 2048 steps.
__device__ unsigned char g_mask[1024 * L_SEQ];   // 2 MB

// ---------------- Kernel A: mask + streaming copy-through ------------------
__global__ __launch_bounds__(A_THREADS)
void mask_copy_kernel(const float4* __restrict__ x, float4* __restrict__ out,
                      int ngroups) {   // ngroups = (B*L)/4
    const int lane = threadIdx.x & 31;
    const int wid  = threadIdx.x >> 5;
    const unsigned FULL = 0xffffffffu;
    const int totalW = gridDim.x * A_WARPS;

    for (int g = blockIdx.x * A_WARPS + wid; g < ngroups; g += totalW) {
        const int r0 = g << 2;  // flattened (b*L + t) row base
        float4 v0 = x[(r0 + 0) * ROW_F4 + lane];
        float4 v1 = x[(r0 + 1) * ROW_F4 + lane];
        float4 v2 = x[(r0 + 2) * ROW_F4 + lane];
        float4 v3 = x[(r0 + 3) * ROW_F4 + lane];

        bool z0 = (fabsf(v0.x) <= ATOL_F) & (fabsf(v0.y) <= ATOL_F) &
                  (fabsf(v0.z) <= ATOL_F) & (fabsf(v0.w) <= ATOL_F);
        bool z1 = (fabsf(v1.x) <= ATOL_F) & (fabsf(v1.y) <= ATOL_F) &
                  (fabsf(v1.z) <= ATOL_F) & (fabsf(v1.w) <= ATOL_F);
        bool z2 = (fabsf(v2.x) <= ATOL_F) & (fabsf(v2.y) <= ATOL_F) &
                  (fabsf(v2.z) <= ATOL_F) & (fabsf(v2.w) <= ATOL_F);
        bool z3 = (fabsf(v3.x) <= ATOL_F) & (fabsf(v3.y) <= ATOL_F) &
                  (fabsf(v3.z) <= ATOL_F) & (fabsf(v3.w) <= ATOL_F);

        unsigned m0 = __all_sync(FULL, z0);
        unsigned m1 = __all_sync(FULL, z1);
        unsigned m2 = __all_sync(FULL, z2);
        unsigned m3 = __all_sync(FULL, z3);

        if (!m0) __stcs(&out[(r0 + 0) * ROW_F4 + lane], v0);
        if (!m1) __stcs(&out[(r0 + 1) * ROW_F4 + lane], v1);
        if (!m2) __stcs(&out[(r0 + 2) * ROW_F4 + lane], v2);
        if (!m3) __stcs(&out[(r0 + 3) * ROW_F4 + lane], v3);

        if (lane == 0) {
            uchar4 mm = make_uchar4((unsigned char)m0, (unsigned char)m1,
                                    (unsigned char)m2, (unsigned char)m3);
            *reinterpret_cast<uchar4*>(&g_mask[r0]) = mm;
        }
    }
}

// ---------------- Kernel B: self-contained compacted gather fill -----------
// grid = B * B_SLICES, 8 warps/CTA, 64 timesteps/warp. Each warp derives all
// forward-fill source indices from mask ballots:
//   src(t) = highest valid index < t within the span, else carry-in found by
//   ballot-scanning backwards in 32-step chunks (expected exactly 1 chunk).
__global__ __launch_bounds__(B_THREADS)
void fill_kernel(const float* __restrict__ x, float* __restrict__ out) {
    const int b     = blockIdx.x >> 2;           // B_SLICES == 4
    const int slice = blockIdx.x & 3;
    const float4* __restrict__ xb =
        reinterpret_cast<const float4*>(x + (size_t)b * L_SEQ * D_FEAT);
    float4* __restrict__ ob =
        reinterpret_cast<float4*>(out + (size_t)b * L_SEQ * D_FEAT);

    __shared__ short s_list[B_WARPS][WARP_SPAN];
    __shared__ short s_src [B_WARPS][WARP_SPAN];

    const int lane = threadIdx.x & 31;
    const int wid  = threadIdx.x >> 5;
    const unsigned FULL = 0xffffffffu;
    const unsigned lt = (1u << lane) - 1u;

    const int s0 = slice * SLICE_LEN + wid * WARP_SPAN;   // span start (in row)
    const int gbase = b * L_SEQ;

    unsigned char m0 = g_mask[gbase + s0 + lane];
    unsigned char m1 = g_mask[gbase + s0 + 32 + lane];

    unsigned miss0 = __ballot_sync(FULL, m0 != 0);
    unsigned miss1 = __ballot_sync(FULL, m1 != 0);
    if ((miss0 | miss1) == 0u) return;          // warp-uniform early exit

    const unsigned valid0 = ~miss0;
    const unsigned valid1 = ~miss1;

    // Carry-in: last valid index before s0 (0 if none -> leading-missing
    // block maps to x[0], matching the reference exactly).
    int carry = 0;
    for (int off = s0 - 32; off >= 0; off -= 32) {
        unsigned char mb = g_mask[gbase + off + lane];
        unsigned vb = ~__ballot_sync(FULL, mb != 0);
        if (vb) { carry = off + (31 - __clz(vb)); break; }
    }

    // Per-lane source index for its own timestep (if missing).
    unsigned vbelow0 = valid0 & lt;
    int src0 = vbelow0 ? (s0 + (31 - __clz(vbelow0))) : carry;

    unsigned vbelow1 = valid1 & lt;
    int src1;
    if (vbelow1)      src1 = s0 + 32 + (31 - __clz(vbelow1));
    else if (valid0)  src1 = s0 + (31 - __clz(valid0));
    else              src1 = carry;

    // Ballot-compact (t, src) pairs into smem work lists.
    const int c0  = __popc(miss0);
    const int cnt = c0 + __popc(miss1);
    if (m0) {
        int p = __popc(miss0 & lt);
        s_list[wid][p] = (short)(s0 + lane);
        s_src [wid][p] = (short)src0;
    }
    if (m1) {
        int p = c0 + __popc(miss1 & lt);
        s_list[wid][p] = (short)(s0 + 32 + lane);
        s_src [wid][p] = (short)src1;
    }
    __syncwarp();

    // Fill: one LDG.128 + STG.128 per lane per missing row, 4 in flight.
    int i = 0;
    for (; i + 4 <= cnt; i += 4) {
        int ta = (int)s_list[wid][i + 0];
        int tb = (int)s_list[wid][i + 1];
        int tc = (int)s_list[wid][i + 2];
        int td = (int)s_list[wid][i + 3];
        int sa = (int)s_src[wid][i + 0];
        int sb = (int)s_src[wid][i + 1];
        int sc = (int)s_src[wid][i + 2];
        int sd = (int)s_src[wid][i + 3];
        float4 va = xb[sa * ROW_F4 + lane];
        float4 vb = xb[sb * ROW_F4 + lane];
        float4 vc = xb[sc * ROW_F4 + lane];
        float4 vd = xb[sd * ROW_F4 + lane];
        __stcs(&ob[ta * ROW_F4 + lane], va);
        __stcs(&ob[tb * ROW_F4 + lane], vb);
        __stcs(&ob[tc * ROW_F4 + lane], vc);
        __stcs(&ob[td * ROW_F4 + lane], vd);
    }
    for (; i < cnt; i++) {
        int t = (int)s_list[wid][i];
        int s = (int)s_src[wid][i];
        __stcs(&ob[t * ROW_F4 + lane], xb[s * ROW_F4 + lane]);
    }
}

extern "C" void kernel_launch(void* const* d_in, const int* in_sizes, int n_in,
                              void* d_out, int out_size) {
    const float* x = (const float*)d_in[0];
    float* out = (float*)d_out;
    const int B = in_sizes[0] / (L_SEQ * D_FEAT);
    const int ngroups = (B * L_SEQ) >> 2;

    mask_copy_kernel<<<A_GRID, A_THREADS>>>(
        reinterpret_cast<const float4*>(x),
        reinterpret_cast<float4*>(out), ngroups);
    fill_kernel<<<B * B_SLICES, B_THREADS>>>(x, out);
}